// round 15
// baseline (speedup 1.0000x reference)
#include <cuda_runtime.h>
#include <cuda_bf16.h>
#include <cuda_fp16.h>
#include <math.h>
#include <cstdint>

#define Bc 32
#define Nn 784
#define DIMc 512
#define Hh 8
#define KDc 32
#define VDc 128
#define QKV_OUTc 1536
#define VAL_ATTNc 1024
#define SCALE 0.17677669529663687f
#define LOG2E 1.4426950408889634f

// ---------------- scratch (static device globals) ----------------
__device__ __nv_bfloat16 g_biasb[Hh * Nn * Nn];    // [h][n][m], pre-scaled by LOG2E
__device__ float g_qs[QKV_OUTc], g_qbb[QKV_OUTc];
__device__ float g_ps[DIMc], g_pbb[DIMc];

// fp16 attention operands
__device__ __half g_qf[Bc * Hh * Nn * KDc];        // [bh][n][32]
__device__ __half g_kf[Bc * Hh * Nn * KDc];
__device__ __half g_vf[Bc * Hh * Nn * VDc];        // [bh][n][128] row-major

// split-bf16 GEMM buffers
__device__ __nv_bfloat16 g_xh[Bc * Nn * DIMc],  g_xl[Bc * Nn * DIMc];
__device__ __nv_bfloat16 g_wqh[QKV_OUTc * DIMc], g_wql[QKV_OUTc * DIMc];
__device__ __nv_bfloat16 g_oh[Bc * Nn * VAL_ATTNc], g_ol[Bc * Nn * VAL_ATTNc];
__device__ __nv_bfloat16 g_wph[DIMc * VAL_ATTNc], g_wpl[DIMc * VAL_ATTNc];

// ---------------- helpers ----------------
static __device__ __forceinline__ unsigned pk_bf(__nv_bfloat16 a, __nv_bfloat16 b) {
    return ((unsigned)__bfloat16_as_ushort(b) << 16) | (unsigned)__bfloat16_as_ushort(a);
}
static __device__ __forceinline__ unsigned pk_f2(float a, float b) {
    return pk_bf(__float2bfloat16(a), __float2bfloat16(b));
}
static __device__ __forceinline__ unsigned pk_h2(float a, float b) {
    __half2 h = __floats2half2_rn(a, b);
    return *(unsigned*)&h;
}
static __device__ __forceinline__ void mma_bf16(float* d, const unsigned* a, const unsigned* b) {
    asm("mma.sync.aligned.m16n8k16.row.col.f32.bf16.bf16.f32 "
        "{%0,%1,%2,%3}, {%4,%5,%6,%7}, {%8,%9}, {%0,%1,%2,%3};"
        : "+f"(d[0]), "+f"(d[1]), "+f"(d[2]), "+f"(d[3])
        : "r"(a[0]), "r"(a[1]), "r"(a[2]), "r"(a[3]), "r"(b[0]), "r"(b[1]));
}
static __device__ __forceinline__ void mma_f16(float* d, const unsigned* a, const unsigned* b) {
    asm("mma.sync.aligned.m16n8k16.row.col.f32.f16.f16.f32 "
        "{%0,%1,%2,%3}, {%4,%5,%6,%7}, {%8,%9}, {%0,%1,%2,%3};"
        : "+f"(d[0]), "+f"(d[1]), "+f"(d[2]), "+f"(d[3])
        : "r"(a[0]), "r"(a[1]), "r"(a[2]), "r"(a[3]), "r"(b[0]), "r"(b[1]));
}
static __device__ __forceinline__ uint32_t sm_u32(const void* p) {
    return (uint32_t)__cvta_generic_to_shared(p);
}
static __device__ __forceinline__ void ldsm4(unsigned* r, uint32_t a) {
    asm volatile("ldmatrix.sync.aligned.m8n8.x4.shared.b16 {%0,%1,%2,%3}, [%4];"
        : "=r"(r[0]), "=r"(r[1]), "=r"(r[2]), "=r"(r[3]) : "r"(a));
}
static __device__ __forceinline__ void ldsm4t(unsigned* r, uint32_t a) {
    asm volatile("ldmatrix.sync.aligned.m8n8.x4.trans.shared.b16 {%0,%1,%2,%3}, [%4];"
        : "=r"(r[0]), "=r"(r[1]), "=r"(r[2]), "=r"(r[3]) : "r"(a));
}
static __device__ __forceinline__ void cpa8(uint32_t d, const void* s, int sz) {
    asm volatile("cp.async.ca.shared.global [%0], [%1], 8, %2;"
        :: "r"(d), "l"(__cvta_generic_to_global(s)), "r"(sz) : "memory");
}
#define CP_COMMIT() asm volatile("cp.async.commit_group;" ::: "memory")
#define CP_WAIT0()  asm volatile("cp.async.wait_group 0;" ::: "memory")

// fast 2^t on fma/alu pipes (MUFU rt=8 is the softmax bottleneck otherwise)
static __device__ __forceinline__ float exp2_fast(float t) {
    t = fmaxf(t, -120.f);
    float r = t + 12582912.f;
    int n = __float_as_int(r) - 0x4B400000;
    float f = t - (r - 12582912.f);
    float g = f * 0.6931471805599453f;
    float p = fmaf(g, 0.0083333333f, 0.0416666667f);
    p = fmaf(p, g, 0.1666666667f);
    p = fmaf(p, g, 0.5f);
    p = fmaf(p, g, 1.0f);
    p = fmaf(p, g, 1.0f);
    return __int_as_float(__float_as_int(p) + (n << 23));
}

// ---------------- BN coefficient folding ----------------
__global__ void bn_coef_kernel(const float* __restrict__ qg, const float* __restrict__ qb,
                               const float* __restrict__ qm, const float* __restrict__ qv,
                               const float* __restrict__ pg, const float* __restrict__ pb,
                               const float* __restrict__ pm, const float* __restrict__ pv) {
    int i = blockIdx.x * 256 + threadIdx.x;
    if (i < QKV_OUTc) {
        float s = qg[i] * rsqrtf(qv[i] + 1e-5f);
        g_qs[i] = s;
        g_qbb[i] = qb[i] - qm[i] * s;
    }
    if (i < DIMc) {
        float s = pg[i] * rsqrtf(pv[i] + 1e-5f);
        g_ps[i] = s;
        g_pbb[i] = pb[i] - pm[i] * s;
    }
}

// ---------------- bias gather: bf16, pre-scaled by LOG2E ----------------
__global__ void bias_kernel(const float* __restrict__ ab, const int* __restrict__ idxs) {
    int nm = blockIdx.x * 256 + threadIdx.x;
    if (nm < Nn * Nn) {
        int idx = idxs[nm];
#pragma unroll
        for (int h = 0; h < Hh; h++)
            g_biasb[h * Nn * Nn + nm] = __float2bfloat16(ab[h * Nn + idx] * LOG2E);
    }
}

// ---------------- fp32 -> hi/lo bf16 conversion (x, qkv_w, proj_w) ----------------
__global__ void cvt_hilo_kernel(const float* __restrict__ s, int which, int n4) {
    int i = blockIdx.x * 256 + threadIdx.x;
    if (i >= n4) return;
    const float4* sp = (const float4*)s;
    __nv_bfloat16 *h, *l;
    if (which == 0)      { h = g_xh;  l = g_xl;  }
    else if (which == 1) { h = g_wqh; l = g_wql; }
    else                 { h = g_wph; l = g_wpl; }
    float4 v = sp[i];
    __nv_bfloat16 h0 = __float2bfloat16(v.x), h1 = __float2bfloat16(v.y);
    __nv_bfloat16 h2 = __float2bfloat16(v.z), h3 = __float2bfloat16(v.w);
    __nv_bfloat16 l0 = __float2bfloat16(v.x - __bfloat162float(h0));
    __nv_bfloat16 l1 = __float2bfloat16(v.y - __bfloat162float(h1));
    __nv_bfloat16 l2 = __float2bfloat16(v.z - __bfloat162float(h2));
    __nv_bfloat16 l3 = __float2bfloat16(v.w - __bfloat162float(h3));
    ((uint2*)h)[i] = make_uint2(pk_bf(h0, h1), pk_bf(h2, h3));
    ((uint2*)l)[i] = make_uint2(pk_bf(l0, l1), pk_bf(l2, l3));
}

// ---------------- qkv scatter: q,k,v -> fp16 ----------------
static __device__ __forceinline__ void qkv_scatter_f(int b, int n, int o, float y0, float y1) {
    int h = o / 192, r = o - h * 192;
    int bh = b * Hh + h;
    unsigned pk = pk_h2(y0, y1);
    __half* arr;
    size_t idx;
    if (r < KDc)            { arr = g_qf; idx = ((size_t)(bh * Nn) + n) * KDc + r; }
    else if (r < 2 * KDc)   { arr = g_kf; idx = ((size_t)(bh * Nn) + n) * KDc + (r - KDc); }
    else                    { arr = g_vf; idx = ((size_t)(bh * Nn) + n) * VDc + (r - 2 * KDc); }
    *(unsigned*)&arr[idx] = pk;
}

// ---------------- split-bf16 mma.sync GEMM, 2-stage cp.async pipeline ----------------
#define SSTR 40
#define GSTG 40960
__global__ __launch_bounds__(256, 2) void mma_gemm_kernel(int mode, float* __restrict__ out) {
    extern __shared__ __align__(16) char dsm[];
    int t = threadIdx.x;
    int lane = t & 31, wid = t >> 5;
    int g = lane >> 2, tg = lane & 3;
    int sub = lane >> 3, rr = lane & 7;
    int warp_m = wid >> 2, warp_n = wid & 3;
    int m0 = blockIdx.x * 128, o0 = blockIdx.y * 128;

    const __nv_bfloat16 *Ah, *Al, *Bh, *Bl;
    int K;
    if (mode == 0) { Ah = g_xh; Al = g_xl; Bh = g_wqh; Bl = g_wql; K = DIMc; }
    else           { Ah = g_oh; Al = g_ol; Bh = g_wph; Bl = g_wpl; K = VAL_ATTNc; }

    uint32_t sb = sm_u32(dsm);
    uint32_t a_off = (uint32_t)(((warp_m * 64 + (sub & 1) * 8 + rr) * SSTR + (sub >> 1) * 8) * 2);
    uint32_t b_off = (sub < 2 ? 20480u : 30720u) +
                     (uint32_t)(((warp_n * 32 + rr) * SSTR + (sub & 1) * 8) * 2);

    float acc[4][4][4];
#pragma unroll
    for (int i = 0; i < 4; i++)
#pragma unroll
        for (int j = 0; j < 4; j++)
#pragma unroll
            for (int c = 0; c < 4; c++) acc[i][j][c] = 0.f;

    int T = K >> 5;
#define G_LOAD(IT, STG) do {                                                      \
        int _k0 = (IT) << 5;                                                      \
        uint32_t _base = sb + (STG) * GSTG;                                       \
        _Pragma("unroll")                                                         \
        for (int ii = 0; ii < 4; ii++) {                                          \
            int e = t + 256 * ii;                                                 \
            int r = e >> 3, c = e & 7;                                            \
            uint32_t so = _base + (uint32_t)(r * 80 + 8 * c);                     \
            size_t gi = (size_t)(m0 + r) * K + _k0 + 4 * c;                       \
            size_t gj = (size_t)(o0 + r) * K + _k0 + 4 * c;                       \
            cpa8(so,         Ah + gi, 8);                                         \
            cpa8(so + 10240, Al + gi, 8);                                         \
            cpa8(so + 20480, Bh + gj, 8);                                         \
            cpa8(so + 30720, Bl + gj, 8);                                         \
        }                                                                         \
        CP_COMMIT();                                                              \
    } while (0)

    G_LOAD(0, 0);
    for (int it = 0; it < T; it++) {
        CP_WAIT0();
        __syncthreads();
        if (it + 1 < T) G_LOAD(it + 1, (it + 1) & 1);
        uint32_t base = sb + (it & 1) * GSTG;
#pragma unroll
        for (int kk = 0; kk < 2; kk++) {
            unsigned ah[4][4], al[4][4], bb[4][4];
#pragma unroll
            for (int mi = 0; mi < 4; mi++) {
                uint32_t off = (uint32_t)((mi * 16 * SSTR + kk * 16) * 2);
                ldsm4(ah[mi], base + a_off + off);
                ldsm4(al[mi], base + 10240 + a_off + off);
            }
#pragma unroll
            for (int nj = 0; nj < 4; nj++)
                ldsm4(bb[nj], base + b_off + (uint32_t)((nj * 8 * SSTR + kk * 16) * 2));
#pragma unroll
            for (int mi = 0; mi < 4; mi++)
#pragma unroll
                for (int nj = 0; nj < 4; nj++) {
                    mma_bf16(acc[mi][nj], ah[mi], bb[nj]);      // hi*hi
                    mma_bf16(acc[mi][nj], ah[mi], bb[nj] + 2);  // hi*lo
                    mma_bf16(acc[mi][nj], al[mi], bb[nj]);      // lo*hi
                }
        }
    }
#undef G_LOAD

#pragma unroll
    for (int mi = 0; mi < 4; mi++) {
        int m_lo = m0 + warp_m * 64 + mi * 16 + g;
        int m_hi = m_lo + 8;
        if (mode == 0) {
            int b0 = m_lo / Nn, n0q = m_lo - b0 * Nn;
            int b1 = m_hi / Nn, n1q = m_hi - b1 * Nn;
#pragma unroll
            for (int nj = 0; nj < 4; nj++) {
                int o = o0 + warp_n * 32 + nj * 8 + 2 * tg;
                qkv_scatter_f(b0, n0q, o, acc[mi][nj][0] * g_qs[o] + g_qbb[o],
                                          acc[mi][nj][1] * g_qs[o + 1] + g_qbb[o + 1]);
                qkv_scatter_f(b1, n1q, o, acc[mi][nj][2] * g_qs[o] + g_qbb[o],
                                          acc[mi][nj][3] * g_qs[o + 1] + g_qbb[o + 1]);
            }
        } else {
#pragma unroll
            for (int nj = 0; nj < 4; nj++) {
                int o = o0 + warp_n * 32 + nj * 8 + 2 * tg;
                float s0 = g_ps[o], s1 = g_ps[o + 1];
                float c0 = g_pbb[o], c1 = g_pbb[o + 1];
                *(float2*)&out[(size_t)m_lo * DIMc + o] =
                    make_float2(acc[mi][nj][0] * s0 + c0, acc[mi][nj][1] * s1 + c1);
                *(float2*)&out[(size_t)m_hi * DIMc + o] =
                    make_float2(acc[mi][nj][2] * s0 + c0, acc[mi][nj][3] * s1 + c1);
            }
        }
    }
}

// ---------------- fp16 tensor-core attention ----------------
// dyn smem: Qf@0 (10240) | stage s @ 10240+s*22528: Kf@0 (5120), Vf@5120 (17408)
#define ASTG 22528
#define ATTN_SMEM_B 55296
#define VROWB 272

__global__ __launch_bounds__(256) void attn_mma_kernel() {
    extern __shared__ __align__(16) char dsm[];
    __half* Qf_s = (__half*)(dsm);

    int n0q = blockIdx.x * 128;
    int h = blockIdx.y, b = blockIdx.z;
    int bh = b * Hh + h;
    int t = threadIdx.x, w = t >> 5, lane = t & 31;
    int g = lane >> 2, tg = lane & 3;
    int sub = lane >> 3, rr = lane & 7;

    const __half* qfB = g_qf + (size_t)(bh * Nn) * KDc;
    const __half* kfB = g_kf + (size_t)(bh * Nn) * KDc;
    const __half* vfB = g_vf + (size_t)(bh * Nn) * VDc;
    const __nv_bfloat16* biasb = g_biasb + (size_t)h * Nn * Nn;

    uint32_t sb = sm_u32(dsm);
    uint32_t q_moff = (uint32_t)(((16 * w + (sub & 1) * 8 + rr) * SSTR + (sub >> 1) * 8) * 2);
    // K frags: mats (nt,k0),(nt,k8),(nt+1,k0),(nt+1,k8)
    uint32_t k_lane = (uint32_t)((((sub >> 1) * 8 + rr) * SSTR + (sub & 1) * 8) * 2);
    // V frags (trans): mats (k0,d0),(k8,d0),(k0,d8),(k8,d8)
    uint32_t v_lane = (uint32_t)(((sub & 1) * 8 + rr) * VROWB + (sub >> 1) * 16);

    // load Q tile (128 x 32 fp16), rows clamped at boundary
#pragma unroll
    for (int e = t; e < 512; e += 256) {
        int r = e >> 2, c = e & 3;
        int n = n0q + r; if (n >= Nn) n = Nn - 1;
        *(uint4*)&Qf_s[r * SSTR + 8 * c] = *(const uint4*)&qfB[(size_t)n * KDc + 8 * c];
    }
    __syncthreads();

    // hoist Q fragments
    unsigned qf[2][4];
#pragma unroll
    for (int kt = 0; kt < 2; kt++)
        ldsm4(qf[kt], sb + q_moff + kt * 32);

#define KV_LOAD(IT, STG) do {                                                     \
        int _m0 = (IT) * 64;                                                      \
        uint32_t _base = sb + 10240u + (STG) * ASTG;                              \
        _Pragma("unroll")                                                         \
        for (int ii = 0; ii < 2; ii++) {                                          \
            int e = t + 256 * ii;                                                 \
            int r = e >> 3, c = e & 7;                                            \
            int m = _m0 + r;                                                      \
            int sz = (m < Nn) ? 8 : 0;                                            \
            int mc = (m < Nn) ? m : 0;                                            \
            cpa8(_base + (uint32_t)(r * 80 + 8 * c), kfB + (size_t)mc * KDc + 4 * c, sz); \
        }                                                                         \
        _Pragma("unroll")                                                         \
        for (int ii = 0; ii < 8; ii++) {                                          \
            int e = t + 256 * ii;                                                 \
            int r = e >> 5, c = e & 31;                                           \
            int m = _m0 + r;                                                      \
            int sz = (m < Nn) ? 8 : 0;                                            \
            int mc = (m < Nn) ? m : 0;                                            \
            cpa8(_base + 5120u + (uint32_t)(r * VROWB + 8 * c),                   \
                 vfB + (size_t)mc * VDc + 4 * c, sz);                             \
        }                                                                         \
        CP_COMMIT();                                                              \
    } while (0)

    float o_acc[16][4];
#pragma unroll
    for (int on = 0; on < 16; on++)
#pragma unroll
        for (int c = 0; c < 4; c++) o_acc[on][c] = 0.f;
    float rs0 = 0.f, rs1 = 0.f;

    int row0 = n0q + 16 * w + g;
    int nc0 = (row0 < Nn) ? row0 : (Nn - 1);
    int nc1 = (row0 + 8 < Nn) ? (row0 + 8) : (Nn - 1);

    const int T = (Nn + 63) / 64;   // 13
    KV_LOAD(0, 0);
    for (int it = 0; it < T; it++) {
        CP_WAIT0();
        __syncthreads();
        if (it + 1 < T) KV_LOAD(it + 1, (it + 1) & 1);
        int m0 = it * 64;
        uint32_t stb = sb + 10240u + (it & 1) * ASTG;
        uint32_t k_base = stb + k_lane;
        uint32_t v_base = stb + 5120u + v_lane;

        // ---- prefetch bias (bf16 pairs, pre-scaled by LOG2E) ----
        unsigned ub0[8], ub1[8];
#pragma unroll
        for (int nt = 0; nt < 8; nt++) {
            int mcol = m0 + 8 * nt + 2 * tg;
            if (mcol < Nn) {
                ub0[nt] = *(const unsigned*)&biasb[(size_t)nc0 * Nn + mcol];
                ub1[nt] = *(const unsigned*)&biasb[(size_t)nc1 * Nn + mcol];
            } else {
                ub0[nt] = 0xC6EAC6EAu;   // bf16(-29952) x2 -> masked
                ub1[nt] = 0xC6EAC6EAu;
            }
        }

        // ---- S = Q K^T (fp16 single product) ----
        float sa[8][4];
#pragma unroll
        for (int nt = 0; nt < 8; nt++)
#pragma unroll
            for (int c = 0; c < 4; c++) sa[nt][c] = 0.f;
#pragma unroll
        for (int kt = 0; kt < 2; kt++) {
#pragma unroll
            for (int ntp = 0; ntp < 4; ntp++) {
                unsigned bb[4];
                ldsm4(bb, k_base + (uint32_t)(ntp * 16 * SSTR * 2 + kt * 32));
                mma_f16(sa[2 * ntp],     qf[kt], bb);
                mma_f16(sa[2 * ntp + 1], qf[kt], bb + 2);
            }
        }

        // ---- bias + exp (poly) -> fp16 P frags in registers ----
        unsigned pf[4][4];
#pragma unroll
        for (int nt = 0; nt < 8; nt++) {
            float b0lo = __uint_as_float(ub0[nt] << 16);
            float b0hi = __uint_as_float(ub0[nt] & 0xffff0000u);
            float b1lo = __uint_as_float(ub1[nt] << 16);
            float b1hi = __uint_as_float(ub1[nt] & 0xffff0000u);
            float p0 = exp2_fast(fmaf(sa[nt][0], SCALE * LOG2E, b0lo));
            float p1 = exp2_fast(fmaf(sa[nt][1], SCALE * LOG2E, b0hi));
            float p2 = exp2_fast(fmaf(sa[nt][2], SCALE * LOG2E, b1lo));
            float p3 = exp2_fast(fmaf(sa[nt][3], SCALE * LOG2E, b1hi));
            rs0 += p0 + p1;
            rs1 += p2 + p3;
            unsigned u01 = pk_h2(p0, p1), u23 = pk_h2(p2, p3);
            int kv = nt >> 1;
            if ((nt & 1) == 0) { pf[kv][0] = u01; pf[kv][1] = u23; }
            else               { pf[kv][2] = u01; pf[kv][3] = u23; }
        }

        // ---- O += P V (fp16 single product; ldmatrix.trans on row-major V) ----
#pragma unroll
        for (int kv = 0; kv < 4; kv++) {
            uint32_t kvb = v_base + (uint32_t)(kv * 16 * VROWB);
#pragma unroll
            for (int op = 0; op < 8; op++) {
                unsigned vv[4];
                ldsm4t(vv, kvb + (uint32_t)(op * 32));
                mma_f16(o_acc[2 * op],     pf[kv], vv);
                mma_f16(o_acc[2 * op + 1], pf[kv], vv + 2);
            }
        }
    }
#undef KV_LOAD

    // reduce row sums across the 4 tg lanes of each group
    rs0 += __shfl_xor_sync(0xffffffffu, rs0, 1);
    rs0 += __shfl_xor_sync(0xffffffffu, rs0, 2);
    rs1 += __shfl_xor_sync(0xffffffffu, rs1, 1);
    rs1 += __shfl_xor_sync(0xffffffffu, rs1, 2);
    float inv0 = 1.f / rs0, inv1 = 1.f / rs1;

    // normalize + hardswish + store split-bf16 for proj GEMM
    int nlo = n0q + 16 * w + g, nhi = nlo + 8;
#pragma unroll
    for (int on = 0; on < 16; on++) {
        int d = h * VDc + 8 * on + 2 * tg;
        if (nlo < Nn) {
            float a0 = o_acc[on][0] * inv0, a1 = o_acc[on][1] * inv0;
            a0 = a0 * fminf(fmaxf(a0 + 3.f, 0.f), 6.f) * (1.f / 6.f);
            a1 = a1 * fminf(fmaxf(a1 + 3.f, 0.f), 6.f) * (1.f / 6.f);
            size_t idx = ((size_t)b * Nn + nlo) * VAL_ATTNc + d;
            __nv_bfloat16 h0 = __float2bfloat16(a0), h1 = __float2bfloat16(a1);
            *(unsigned*)&g_oh[idx] = pk_bf(h0, h1);
            *(unsigned*)&g_ol[idx] = pk_f2(a0 - __bfloat162float(h0), a1 - __bfloat162float(h1));
        }
        if (nhi < Nn) {
            float a2 = o_acc[on][2] * inv1, a3 = o_acc[on][3] * inv1;
            a2 = a2 * fminf(fmaxf(a2 + 3.f, 0.f), 6.f) * (1.f / 6.f);
            a3 = a3 * fminf(fmaxf(a3 + 3.f, 0.f), 6.f) * (1.f / 6.f);
            size_t idx = ((size_t)b * Nn + nhi) * VAL_ATTNc + d;
            __nv_bfloat16 h2 = __float2bfloat16(a2), h3 = __float2bfloat16(a3);
            *(unsigned*)&g_oh[idx] = pk_bf(h2, h3);
            *(unsigned*)&g_ol[idx] = pk_f2(a2 - __bfloat162float(h2), a3 - __bfloat162float(h3));
        }
    }
}

// ---------------- launch ----------------
extern "C" void kernel_launch(void* const* d_in, const int* in_sizes, int n_in,
                              void* d_out, int out_size) {
    (void)in_sizes; (void)n_in; (void)out_size;
    const float* x      = (const float*)d_in[0];
    const float* qkv_w  = (const float*)d_in[1];
    const float* qkv_g  = (const float*)d_in[2];
    const float* qkv_b  = (const float*)d_in[3];
    const float* qkv_m  = (const float*)d_in[4];
    const float* qkv_v  = (const float*)d_in[5];
    const float* ab     = (const float*)d_in[6];
    const float* proj_w = (const float*)d_in[7];
    const float* proj_g = (const float*)d_in[8];
    const float* proj_b = (const float*)d_in[9];
    const float* proj_m = (const float*)d_in[10];
    const float* proj_v = (const float*)d_in[11];
    const int*   idxs   = (const int*)d_in[12];
    float* out = (float*)d_out;

    bn_coef_kernel<<<6, 256>>>(qkv_g, qkv_b, qkv_m, qkv_v, proj_g, proj_b, proj_m, proj_v);
    bias_kernel<<<(Nn * Nn + 255) / 256, 256>>>(ab, idxs);

    cvt_hilo_kernel<<<(Bc * Nn * DIMc / 4 + 255) / 256, 256>>>(x, 0, Bc * Nn * DIMc / 4);
    cvt_hilo_kernel<<<(QKV_OUTc * DIMc / 4 + 255) / 256, 256>>>(qkv_w, 1, QKV_OUTc * DIMc / 4);
    cvt_hilo_kernel<<<(DIMc * VAL_ATTNc / 4 + 255) / 256, 256>>>(proj_w, 3, DIMc * VAL_ATTNc / 4);

    cudaFuncSetAttribute(mma_gemm_kernel, cudaFuncAttributeMaxDynamicSharedMemorySize, 2 * GSTG);
    mma_gemm_kernel<<<dim3(196, 12), 256, 2 * GSTG>>>(0, nullptr);   // QKV

    cudaFuncSetAttribute(attn_mma_kernel, cudaFuncAttributeMaxDynamicSharedMemorySize, ATTN_SMEM_B);
    attn_mma_kernel<<<dim3(7, Hh, Bc), 256, ATTN_SMEM_B>>>();

    mma_gemm_kernel<<<dim3(196, 4), 256, 2 * GSTG>>>(1, out);        // proj
}

// round 16
// speedup vs baseline: 1.8459x; 1.8459x over previous
#include <cuda_runtime.h>
#include <cuda_bf16.h>
#include <cuda_fp16.h>
#include <math.h>
#include <cstdint>

#define Bc 32
#define Nn 784
#define DIMc 512
#define Hh 8
#define KDc 32
#define VDc 128
#define QKV_OUTc 1536
#define VAL_ATTNc 1024
#define SCALE 0.17677669529663687f
#define LOG2E 1.4426950408889634f

// ---------------- scratch (static device globals) ----------------
__device__ __nv_bfloat16 g_biasb[Hh * Nn * Nn];    // [h][n][m], pre-scaled by LOG2E
__device__ float g_qs[QKV_OUTc], g_qbb[QKV_OUTc];
__device__ float g_ps[DIMc], g_pbb[DIMc];

// fp16 operands
__device__ __half g_xf[Bc * Nn * DIMc];            // x as fp16
__device__ __half g_wqf[QKV_OUTc * DIMc];          // qkv_w as fp16
__device__ __half g_qf[Bc * Hh * Nn * KDc];        // [bh][n][32]
__device__ __half g_kf[Bc * Hh * Nn * KDc];
__device__ __half g_vf[Bc * Hh * Nn * VDc];        // [bh][n][128] row-major

// split-bf16 proj buffers
__device__ __nv_bfloat16 g_oh[Bc * Nn * VAL_ATTNc], g_ol[Bc * Nn * VAL_ATTNc];
__device__ __nv_bfloat16 g_wph[DIMc * VAL_ATTNc], g_wpl[DIMc * VAL_ATTNc];

// ---------------- helpers ----------------
static __device__ __forceinline__ unsigned pk_bf(__nv_bfloat16 a, __nv_bfloat16 b) {
    return ((unsigned)__bfloat16_as_ushort(b) << 16) | (unsigned)__bfloat16_as_ushort(a);
}
static __device__ __forceinline__ unsigned pk_f2(float a, float b) {
    return pk_bf(__float2bfloat16(a), __float2bfloat16(b));
}
static __device__ __forceinline__ unsigned pk_h2(float a, float b) {
    __half2 h = __floats2half2_rn(a, b);
    return *(unsigned*)&h;
}
static __device__ __forceinline__ void mma_bf16(float* d, const unsigned* a, const unsigned* b) {
    asm("mma.sync.aligned.m16n8k16.row.col.f32.bf16.bf16.f32 "
        "{%0,%1,%2,%3}, {%4,%5,%6,%7}, {%8,%9}, {%0,%1,%2,%3};"
        : "+f"(d[0]), "+f"(d[1]), "+f"(d[2]), "+f"(d[3])
        : "r"(a[0]), "r"(a[1]), "r"(a[2]), "r"(a[3]), "r"(b[0]), "r"(b[1]));
}
static __device__ __forceinline__ void mma_f16(float* d, const unsigned* a, const unsigned* b) {
    asm("mma.sync.aligned.m16n8k16.row.col.f32.f16.f16.f32 "
        "{%0,%1,%2,%3}, {%4,%5,%6,%7}, {%8,%9}, {%0,%1,%2,%3};"
        : "+f"(d[0]), "+f"(d[1]), "+f"(d[2]), "+f"(d[3])
        : "r"(a[0]), "r"(a[1]), "r"(a[2]), "r"(a[3]), "r"(b[0]), "r"(b[1]));
}
static __device__ __forceinline__ uint32_t sm_u32(const void* p) {
    return (uint32_t)__cvta_generic_to_shared(p);
}
static __device__ __forceinline__ void ldsm4(unsigned* r, uint32_t a) {
    asm volatile("ldmatrix.sync.aligned.m8n8.x4.shared.b16 {%0,%1,%2,%3}, [%4];"
        : "=r"(r[0]), "=r"(r[1]), "=r"(r[2]), "=r"(r[3]) : "r"(a));
}
static __device__ __forceinline__ void ldsm4t(unsigned* r, uint32_t a) {
    asm volatile("ldmatrix.sync.aligned.m8n8.x4.trans.shared.b16 {%0,%1,%2,%3}, [%4];"
        : "=r"(r[0]), "=r"(r[1]), "=r"(r[2]), "=r"(r[3]) : "r"(a));
}
static __device__ __forceinline__ void cpa8(uint32_t d, const void* s, int sz) {
    asm volatile("cp.async.ca.shared.global [%0], [%1], 8, %2;"
        :: "r"(d), "l"(__cvta_generic_to_global(s)), "r"(sz) : "memory");
}
#define CP_COMMIT() asm volatile("cp.async.commit_group;" ::: "memory")
#define CP_WAIT0()  asm volatile("cp.async.wait_group 0;" ::: "memory")

// fast 2^t on fma/alu pipes (MUFU rt=8 is the softmax bottleneck otherwise)
static __device__ __forceinline__ float exp2_fast(float t) {
    t = fmaxf(t, -120.f);
    float r = t + 12582912.f;
    int n = __float_as_int(r) - 0x4B400000;
    float f = t - (r - 12582912.f);
    float g = f * 0.6931471805599453f;
    float p = fmaf(g, 0.0083333333f, 0.0416666667f);
    p = fmaf(p, g, 0.1666666667f);
    p = fmaf(p, g, 0.5f);
    p = fmaf(p, g, 1.0f);
    p = fmaf(p, g, 1.0f);
    return __int_as_float(__float_as_int(p) + (n << 23));
}

// ---------------- BN coefficient folding ----------------
__global__ void bn_coef_kernel(const float* __restrict__ qg, const float* __restrict__ qb,
                               const float* __restrict__ qm, const float* __restrict__ qv,
                               const float* __restrict__ pg, const float* __restrict__ pb,
                               const float* __restrict__ pm, const float* __restrict__ pv) {
    int i = blockIdx.x * 256 + threadIdx.x;
    if (i < QKV_OUTc) {
        float s = qg[i] * rsqrtf(qv[i] + 1e-5f);
        g_qs[i] = s;
        g_qbb[i] = qb[i] - qm[i] * s;
    }
    if (i < DIMc) {
        float s = pg[i] * rsqrtf(pv[i] + 1e-5f);
        g_ps[i] = s;
        g_pbb[i] = pb[i] - pm[i] * s;
    }
}

// ---------------- bias gather: bf16, pre-scaled by LOG2E ----------------
__global__ void bias_kernel(const float* __restrict__ ab, const int* __restrict__ idxs) {
    int nm = blockIdx.x * 256 + threadIdx.x;
    if (nm < Nn * Nn) {
        int idx = idxs[nm];
#pragma unroll
        for (int h = 0; h < Hh; h++)
            g_biasb[h * Nn * Nn + nm] = __float2bfloat16(ab[h * Nn + idx] * LOG2E);
    }
}

// ---------------- fp32 -> fp16 conversion (x, qkv_w) ----------------
__global__ void cvt_f16_kernel(const float* __restrict__ s, int which, int n4) {
    int i = blockIdx.x * 256 + threadIdx.x;
    if (i >= n4) return;
    __half* d = (which == 0) ? g_xf : g_wqf;
    float4 v = ((const float4*)s)[i];
    ((uint2*)d)[i] = make_uint2(pk_h2(v.x, v.y), pk_h2(v.z, v.w));
}

// ---------------- fp32 -> hi/lo bf16 conversion (proj_w) ----------------
__global__ void cvt_hilo_kernel(const float* __restrict__ s, int n4) {
    int i = blockIdx.x * 256 + threadIdx.x;
    if (i >= n4) return;
    float4 v = ((const float4*)s)[i];
    __nv_bfloat16 h0 = __float2bfloat16(v.x), h1 = __float2bfloat16(v.y);
    __nv_bfloat16 h2 = __float2bfloat16(v.z), h3 = __float2bfloat16(v.w);
    __nv_bfloat16 l0 = __float2bfloat16(v.x - __bfloat162float(h0));
    __nv_bfloat16 l1 = __float2bfloat16(v.y - __bfloat162float(h1));
    __nv_bfloat16 l2 = __float2bfloat16(v.z - __bfloat162float(h2));
    __nv_bfloat16 l3 = __float2bfloat16(v.w - __bfloat162float(h3));
    ((uint2*)g_wph)[i] = make_uint2(pk_bf(h0, h1), pk_bf(h2, h3));
    ((uint2*)g_wpl)[i] = make_uint2(pk_bf(l0, l1), pk_bf(l2, l3));
}

// ---------------- qkv scatter: q,k,v -> fp16 ----------------
static __device__ __forceinline__ void qkv_scatter_f(int b, int n, int o, float y0, float y1) {
    int h = o / 192, r = o - h * 192;
    int bh = b * Hh + h;
    unsigned pk = pk_h2(y0, y1);
    __half* arr;
    size_t idx;
    if (r < KDc)            { arr = g_qf; idx = ((size_t)(bh * Nn) + n) * KDc + r; }
    else if (r < 2 * KDc)   { arr = g_kf; idx = ((size_t)(bh * Nn) + n) * KDc + (r - KDc); }
    else                    { arr = g_vf; idx = ((size_t)(bh * Nn) + n) * VDc + (r - 2 * KDc); }
    *(unsigned*)&arr[idx] = pk;
}

#define SSTR 40

// ---------------- QKV GEMM: single fp16 product, 2-stage cp.async ----------------
// per-20480B stage: A@0 (128x32 fp16, 80B rows), B@10240 (128x32 fp16)
#define G16STG 20480
__global__ __launch_bounds__(256, 2) void qkv_gemm_f16() {
    extern __shared__ __align__(16) char dsm[];
    int t = threadIdx.x;
    int lane = t & 31, wid = t >> 5;
    int g = lane >> 2, tg = lane & 3;
    int sub = lane >> 3, rr = lane & 7;
    int warp_m = wid >> 2, warp_n = wid & 3;
    int m0 = blockIdx.x * 128, o0 = blockIdx.y * 128;
    const int K = DIMc;

    uint32_t sb = sm_u32(dsm);
    uint32_t a_off = (uint32_t)(((warp_m * 64 + (sub & 1) * 8 + rr) * SSTR + (sub >> 1) * 8) * 2);
    // B frags: 2 n-tiles per x4: mats (n+0..7,k0),(n+0..7,k8),(n+8..15,k0),(n+8..15,k8)
    uint32_t b_off = 10240u +
        (uint32_t)(((warp_n * 32 + (sub >> 1) * 8 + rr) * SSTR + (sub & 1) * 8) * 2);

    float acc[4][4][4];
#pragma unroll
    for (int i = 0; i < 4; i++)
#pragma unroll
        for (int j = 0; j < 4; j++)
#pragma unroll
            for (int c = 0; c < 4; c++) acc[i][j][c] = 0.f;

    const int T = K >> 5;   // 16
#define Q_LOAD(IT, STG) do {                                                      \
        int _k0 = (IT) << 5;                                                      \
        uint32_t _base = sb + (STG) * G16STG;                                     \
        _Pragma("unroll")                                                         \
        for (int ii = 0; ii < 4; ii++) {                                          \
            int e = t + 256 * ii;                                                 \
            int r = e >> 3, c = e & 7;                                            \
            uint32_t so = _base + (uint32_t)(r * 80 + 8 * c);                     \
            cpa8(so,          g_xf  + (size_t)(m0 + r) * K + _k0 + 4 * c, 8);     \
            cpa8(so + 10240u, g_wqf + (size_t)(o0 + r) * K + _k0 + 4 * c, 8);     \
        }                                                                         \
        CP_COMMIT();                                                              \
    } while (0)

    Q_LOAD(0, 0);
    for (int it = 0; it < T; it++) {
        CP_WAIT0();
        __syncthreads();
        if (it + 1 < T) Q_LOAD(it + 1, (it + 1) & 1);
        uint32_t base = sb + (it & 1) * G16STG;
#pragma unroll
        for (int kk = 0; kk < 2; kk++) {
            unsigned ah[4][4], bb[2][4];
#pragma unroll
            for (int mi = 0; mi < 4; mi++)
                ldsm4(ah[mi], base + a_off + (uint32_t)((mi * 16 * SSTR + kk * 16) * 2));
#pragma unroll
            for (int njp = 0; njp < 2; njp++)
                ldsm4(bb[njp], base + b_off + (uint32_t)((njp * 16 * SSTR + kk * 16) * 2));
#pragma unroll
            for (int mi = 0; mi < 4; mi++)
#pragma unroll
                for (int njp = 0; njp < 2; njp++) {
                    mma_f16(acc[mi][2 * njp],     ah[mi], bb[njp]);
                    mma_f16(acc[mi][2 * njp + 1], ah[mi], bb[njp] + 2);
                }
        }
    }
#undef Q_LOAD

#pragma unroll
    for (int mi = 0; mi < 4; mi++) {
        int m_lo = m0 + warp_m * 64 + mi * 16 + g;
        int m_hi = m_lo + 8;
        int b0 = m_lo / Nn, n0q = m_lo - b0 * Nn;
        int b1 = m_hi / Nn, n1q = m_hi - b1 * Nn;
#pragma unroll
        for (int nj = 0; nj < 4; nj++) {
            int o = o0 + warp_n * 32 + nj * 8 + 2 * tg;
            qkv_scatter_f(b0, n0q, o, acc[mi][nj][0] * g_qs[o] + g_qbb[o],
                                      acc[mi][nj][1] * g_qs[o + 1] + g_qbb[o + 1]);
            qkv_scatter_f(b1, n1q, o, acc[mi][nj][2] * g_qs[o] + g_qbb[o],
                                      acc[mi][nj][3] * g_qs[o + 1] + g_qbb[o + 1]);
        }
    }
}

// ---------------- proj GEMM: split-bf16 3-product, 2-stage cp.async ----------------
#define GSTG 40960
__global__ __launch_bounds__(256, 2) void proj_gemm_kernel(float* __restrict__ out) {
    extern __shared__ __align__(16) char dsm[];
    int t = threadIdx.x;
    int lane = t & 31, wid = t >> 5;
    int g = lane >> 2, tg = lane & 3;
    int sub = lane >> 3, rr = lane & 7;
    int warp_m = wid >> 2, warp_n = wid & 3;
    int m0 = blockIdx.x * 128, o0 = blockIdx.y * 128;
    const int K = VAL_ATTNc;

    uint32_t sb = sm_u32(dsm);
    uint32_t a_off = (uint32_t)(((warp_m * 64 + (sub & 1) * 8 + rr) * SSTR + (sub >> 1) * 8) * 2);
    uint32_t b_off = (sub < 2 ? 20480u : 30720u) +
                     (uint32_t)(((warp_n * 32 + rr) * SSTR + (sub & 1) * 8) * 2);

    float acc[4][4][4];
#pragma unroll
    for (int i = 0; i < 4; i++)
#pragma unroll
        for (int j = 0; j < 4; j++)
#pragma unroll
            for (int c = 0; c < 4; c++) acc[i][j][c] = 0.f;

    const int T = K >> 5;   // 32
#define G_LOAD(IT, STG) do {                                                      \
        int _k0 = (IT) << 5;                                                      \
        uint32_t _base = sb + (STG) * GSTG;                                       \
        _Pragma("unroll")                                                         \
        for (int ii = 0; ii < 4; ii++) {                                          \
            int e = t + 256 * ii;                                                 \
            int r = e >> 3, c = e & 7;                                            \
            uint32_t so = _base + (uint32_t)(r * 80 + 8 * c);                     \
            size_t gi = (size_t)(m0 + r) * K + _k0 + 4 * c;                       \
            size_t gj = (size_t)(o0 + r) * K + _k0 + 4 * c;                       \
            cpa8(so,         g_oh  + gi, 8);                                      \
            cpa8(so + 10240, g_ol  + gi, 8);                                      \
            cpa8(so + 20480, g_wph + gj, 8);                                      \
            cpa8(so + 30720, g_wpl + gj, 8);                                      \
        }                                                                         \
        CP_COMMIT();                                                              \
    } while (0)

    G_LOAD(0, 0);
    for (int it = 0; it < T; it++) {
        CP_WAIT0();
        __syncthreads();
        if (it + 1 < T) G_LOAD(it + 1, (it + 1) & 1);
        uint32_t base = sb + (it & 1) * GSTG;
#pragma unroll
        for (int kk = 0; kk < 2; kk++) {
            unsigned ah[4][4], al[4][4], bb[4][4];
#pragma unroll
            for (int mi = 0; mi < 4; mi++) {
                uint32_t off = (uint32_t)((mi * 16 * SSTR + kk * 16) * 2);
                ldsm4(ah[mi], base + a_off + off);
                ldsm4(al[mi], base + 10240 + a_off + off);
            }
#pragma unroll
            for (int nj = 0; nj < 4; nj++)
                ldsm4(bb[nj], base + b_off + (uint32_t)((nj * 8 * SSTR + kk * 16) * 2));
#pragma unroll
            for (int mi = 0; mi < 4; mi++)
#pragma unroll
                for (int nj = 0; nj < 4; nj++) {
                    mma_bf16(acc[mi][nj], ah[mi], bb[nj]);      // hi*hi
                    mma_bf16(acc[mi][nj], ah[mi], bb[nj] + 2);  // hi*lo
                    mma_bf16(acc[mi][nj], al[mi], bb[nj]);      // lo*hi
                }
        }
    }
#undef G_LOAD

#pragma unroll
    for (int mi = 0; mi < 4; mi++) {
        int m_lo = m0 + warp_m * 64 + mi * 16 + g;
        int m_hi = m_lo + 8;
#pragma unroll
        for (int nj = 0; nj < 4; nj++) {
            int o = o0 + warp_n * 32 + nj * 8 + 2 * tg;
            float s0 = g_ps[o], s1 = g_ps[o + 1];
            float c0 = g_pbb[o], c1 = g_pbb[o + 1];
            *(float2*)&out[(size_t)m_lo * DIMc + o] =
                make_float2(acc[mi][nj][0] * s0 + c0, acc[mi][nj][1] * s1 + c1);
            *(float2*)&out[(size_t)m_hi * DIMc + o] =
                make_float2(acc[mi][nj][2] * s0 + c0, acc[mi][nj][3] * s1 + c1);
        }
    }
}

// ---------------- fp16 tensor-core attention ----------------
// dyn smem: Qf@0 (10240) | stage s @ 10240+s*22528: Kf@0 (5120), Vf@5120 (17408)
#define ASTG 22528
#define ATTN_SMEM_B 55296
#define VROWB 272

__global__ __launch_bounds__(256) void attn_mma_kernel() {
    extern __shared__ __align__(16) char dsm[];
    __half* Qf_s = (__half*)(dsm);

    int n0q = blockIdx.x * 128;
    int h = blockIdx.y, b = blockIdx.z;
    int bh = b * Hh + h;
    int t = threadIdx.x, w = t >> 5, lane = t & 31;
    int g = lane >> 2, tg = lane & 3;
    int sub = lane >> 3, rr = lane & 7;

    const __half* qfB = g_qf + (size_t)(bh * Nn) * KDc;
    const __half* kfB = g_kf + (size_t)(bh * Nn) * KDc;
    const __half* vfB = g_vf + (size_t)(bh * Nn) * VDc;
    const __nv_bfloat16* biasb = g_biasb + (size_t)h * Nn * Nn;

    uint32_t sb = sm_u32(dsm);
    uint32_t q_moff = (uint32_t)(((16 * w + (sub & 1) * 8 + rr) * SSTR + (sub >> 1) * 8) * 2);
    uint32_t k_lane = (uint32_t)((((sub >> 1) * 8 + rr) * SSTR + (sub & 1) * 8) * 2);
    uint32_t v_lane = (uint32_t)(((sub & 1) * 8 + rr) * VROWB + (sub >> 1) * 16);

    // load Q tile (128 x 32 fp16), rows clamped at boundary
#pragma unroll
    for (int e = t; e < 512; e += 256) {
        int r = e >> 2, c = e & 3;
        int n = n0q + r; if (n >= Nn) n = Nn - 1;
        *(uint4*)&Qf_s[r * SSTR + 8 * c] = *(const uint4*)&qfB[(size_t)n * KDc + 8 * c];
    }
    __syncthreads();

    // hoist Q fragments
    unsigned qf[2][4];
#pragma unroll
    for (int kt = 0; kt < 2; kt++)
        ldsm4(qf[kt], sb + q_moff + kt * 32);

#define KV_LOAD(IT, STG) do {                                                     \
        int _m0 = (IT) * 64;                                                      \
        uint32_t _base = sb + 10240u + (STG) * ASTG;                              \
        _Pragma("unroll")                                                         \
        for (int ii = 0; ii < 2; ii++) {                                          \
            int e = t + 256 * ii;                                                 \
            int r = e >> 3, c = e & 7;                                            \
            int m = _m0 + r;                                                      \
            int sz = (m < Nn) ? 8 : 0;                                            \
            int mc = (m < Nn) ? m : 0;                                            \
            cpa8(_base + (uint32_t)(r * 80 + 8 * c), kfB + (size_t)mc * KDc + 4 * c, sz); \
        }                                                                         \
        _Pragma("unroll")                                                         \
        for (int ii = 0; ii < 8; ii++) {                                          \
            int e = t + 256 * ii;                                                 \
            int r = e >> 5, c = e & 31;                                           \
            int m = _m0 + r;                                                      \
            int sz = (m < Nn) ? 8 : 0;                                            \
            int mc = (m < Nn) ? m : 0;                                            \
            cpa8(_base + 5120u + (uint32_t)(r * VROWB + 8 * c),                   \
                 vfB + (size_t)mc * VDc + 4 * c, sz);                             \
        }                                                                         \
        CP_COMMIT();                                                              \
    } while (0)

    float o_acc[16][4];
#pragma unroll
    for (int on = 0; on < 16; on++)
#pragma unroll
        for (int c = 0; c < 4; c++) o_acc[on][c] = 0.f;
    float rs0 = 0.f, rs1 = 0.f;

    int row0 = n0q + 16 * w + g;
    int nc0 = (row0 < Nn) ? row0 : (Nn - 1);
    int nc1 = (row0 + 8 < Nn) ? (row0 + 8) : (Nn - 1);

    const int T = (Nn + 63) / 64;   // 13
    KV_LOAD(0, 0);
    for (int it = 0; it < T; it++) {
        CP_WAIT0();
        __syncthreads();
        if (it + 1 < T) KV_LOAD(it + 1, (it + 1) & 1);
        int m0 = it * 64;
        uint32_t stb = sb + 10240u + (it & 1) * ASTG;
        uint32_t k_base = stb + k_lane;
        uint32_t v_base = stb + 5120u + v_lane;

        // ---- prefetch bias (bf16 pairs, pre-scaled by LOG2E) ----
        unsigned ub0[8], ub1[8];
#pragma unroll
        for (int nt = 0; nt < 8; nt++) {
            int mcol = m0 + 8 * nt + 2 * tg;
            if (mcol < Nn) {
                ub0[nt] = *(const unsigned*)&biasb[(size_t)nc0 * Nn + mcol];
                ub1[nt] = *(const unsigned*)&biasb[(size_t)nc1 * Nn + mcol];
            } else {
                ub0[nt] = 0xC6EAC6EAu;
                ub1[nt] = 0xC6EAC6EAu;
            }
        }

        // ---- S = Q K^T (fp16 single product) ----
        float sa[8][4];
#pragma unroll
        for (int nt = 0; nt < 8; nt++)
#pragma unroll
            for (int c = 0; c < 4; c++) sa[nt][c] = 0.f;
#pragma unroll
        for (int kt = 0; kt < 2; kt++) {
#pragma unroll
            for (int ntp = 0; ntp < 4; ntp++) {
                unsigned bb[4];
                ldsm4(bb, k_base + (uint32_t)(ntp * 16 * SSTR * 2 + kt * 32));
                mma_f16(sa[2 * ntp],     qf[kt], bb);
                mma_f16(sa[2 * ntp + 1], qf[kt], bb + 2);
            }
        }

        // ---- bias + exp (poly) -> fp16 P frags in registers ----
        unsigned pf[4][4];
#pragma unroll
        for (int nt = 0; nt < 8; nt++) {
            float b0lo = __uint_as_float(ub0[nt] << 16);
            float b0hi = __uint_as_float(ub0[nt] & 0xffff0000u);
            float b1lo = __uint_as_float(ub1[nt] << 16);
            float b1hi = __uint_as_float(ub1[nt] & 0xffff0000u);
            float p0 = exp2_fast(fmaf(sa[nt][0], SCALE * LOG2E, b0lo));
            float p1 = exp2_fast(fmaf(sa[nt][1], SCALE * LOG2E, b0hi));
            float p2 = exp2_fast(fmaf(sa[nt][2], SCALE * LOG2E, b1lo));
            float p3 = exp2_fast(fmaf(sa[nt][3], SCALE * LOG2E, b1hi));
            rs0 += p0 + p1;
            rs1 += p2 + p3;
            unsigned u01 = pk_h2(p0, p1), u23 = pk_h2(p2, p3);
            int kv = nt >> 1;
            if ((nt & 1) == 0) { pf[kv][0] = u01; pf[kv][1] = u23; }
            else               { pf[kv][2] = u01; pf[kv][3] = u23; }
        }

        // ---- O += P V (fp16; ldmatrix.trans on row-major V) ----
#pragma unroll
        for (int kv = 0; kv < 4; kv++) {
            uint32_t kvb = v_base + (uint32_t)(kv * 16 * VROWB);
#pragma unroll
            for (int op = 0; op < 8; op++) {
                unsigned vv[4];
                ldsm4t(vv, kvb + (uint32_t)(op * 32));
                mma_f16(o_acc[2 * op],     pf[kv], vv);
                mma_f16(o_acc[2 * op + 1], pf[kv], vv + 2);
            }
        }
    }
#undef KV_LOAD

    // reduce row sums across the 4 tg lanes of each group
    rs0 += __shfl_xor_sync(0xffffffffu, rs0, 1);
    rs0 += __shfl_xor_sync(0xffffffffu, rs0, 2);
    rs1 += __shfl_xor_sync(0xffffffffu, rs1, 1);
    rs1 += __shfl_xor_sync(0xffffffffu, rs1, 2);
    float inv0 = 1.f / rs0, inv1 = 1.f / rs1;

    // normalize + hardswish + store split-bf16 for proj GEMM
    int nlo = n0q + 16 * w + g, nhi = nlo + 8;
#pragma unroll
    for (int on = 0; on < 16; on++) {
        int d = h * VDc + 8 * on + 2 * tg;
        if (nlo < Nn) {
            float a0 = o_acc[on][0] * inv0, a1 = o_acc[on][1] * inv0;
            a0 = a0 * fminf(fmaxf(a0 + 3.f, 0.f), 6.f) * (1.f / 6.f);
            a1 = a1 * fminf(fmaxf(a1 + 3.f, 0.f), 6.f) * (1.f / 6.f);
            size_t idx = ((size_t)b * Nn + nlo) * VAL_ATTNc + d;
            __nv_bfloat16 h0 = __float2bfloat16(a0), h1 = __float2bfloat16(a1);
            *(unsigned*)&g_oh[idx] = pk_bf(h0, h1);
            *(unsigned*)&g_ol[idx] = pk_f2(a0 - __bfloat162float(h0), a1 - __bfloat162float(h1));
        }
        if (nhi < Nn) {
            float a2 = o_acc[on][2] * inv1, a3 = o_acc[on][3] * inv1;
            a2 = a2 * fminf(fmaxf(a2 + 3.f, 0.f), 6.f) * (1.f / 6.f);
            a3 = a3 * fminf(fmaxf(a3 + 3.f, 0.f), 6.f) * (1.f / 6.f);
            size_t idx = ((size_t)b * Nn + nhi) * VAL_ATTNc + d;
            __nv_bfloat16 h2 = __float2bfloat16(a2), h3 = __float2bfloat16(a3);
            *(unsigned*)&g_oh[idx] = pk_bf(h2, h3);
            *(unsigned*)&g_ol[idx] = pk_f2(a2 - __bfloat162float(h2), a3 - __bfloat162float(h3));
        }
    }
}

// ---------------- launch ----------------
extern "C" void kernel_launch(void* const* d_in, const int* in_sizes, int n_in,
                              void* d_out, int out_size) {
    (void)in_sizes; (void)n_in; (void)out_size;
    const float* x      = (const float*)d_in[0];
    const float* qkv_w  = (const float*)d_in[1];
    const float* qkv_g  = (const float*)d_in[2];
    const float* qkv_b  = (const float*)d_in[3];
    const float* qkv_m  = (const float*)d_in[4];
    const float* qkv_v  = (const float*)d_in[5];
    const float* ab     = (const float*)d_in[6];
    const float* proj_w = (const float*)d_in[7];
    const float* proj_g = (const float*)d_in[8];
    const float* proj_b = (const float*)d_in[9];
    const float* proj_m = (const float*)d_in[10];
    const float* proj_v = (const float*)d_in[11];
    const int*   idxs   = (const int*)d_in[12];
    float* out = (float*)d_out;

    bn_coef_kernel<<<6, 256>>>(qkv_g, qkv_b, qkv_m, qkv_v, proj_g, proj_b, proj_m, proj_v);
    bias_kernel<<<(Nn * Nn + 255) / 256, 256>>>(ab, idxs);

    cvt_f16_kernel<<<(Bc * Nn * DIMc / 4 + 255) / 256, 256>>>(x, 0, Bc * Nn * DIMc / 4);
    cvt_f16_kernel<<<(QKV_OUTc * DIMc / 4 + 255) / 256, 256>>>(qkv_w, 1, QKV_OUTc * DIMc / 4);
    cvt_hilo_kernel<<<(DIMc * VAL_ATTNc / 4 + 255) / 256, 256>>>(proj_w, DIMc * VAL_ATTNc / 4);

    qkv_gemm_f16<<<dim3(196, 12), 256, 2 * G16STG>>>();

    cudaFuncSetAttribute(attn_mma_kernel, cudaFuncAttributeMaxDynamicSharedMemorySize, ATTN_SMEM_B);
    attn_mma_kernel<<<dim3(7, Hh, Bc), 256, ATTN_SMEM_B>>>();

    cudaFuncSetAttribute(proj_gemm_kernel, cudaFuncAttributeMaxDynamicSharedMemorySize, 2 * GSTG);
    proj_gemm_kernel<<<dim3(196, 4), 256, 2 * GSTG>>>(out);
}

// round 17
// speedup vs baseline: 2.3044x; 1.2484x over previous
#include <cuda_runtime.h>
#include <cuda_bf16.h>
#include <cuda_fp16.h>
#include <math.h>
#include <cstdint>

#define Bc 32
#define Nn 784
#define DIMc 512
#define Hh 8
#define KDc 32
#define VDc 128
#define QKV_OUTc 1536
#define VAL_ATTNc 1024
#define SCALE 0.17677669529663687f
#define LOG2E 1.4426950408889634f

// ---------------- scratch (static device globals) ----------------
__device__ __nv_bfloat16 g_biasb[Hh * Nn * Nn];    // [h][n][m], pre-scaled by LOG2E
__device__ float g_qs[QKV_OUTc], g_qbb[QKV_OUTc];
__device__ float g_ps[DIMc], g_pbb[DIMc];

// fp16 operands
__device__ __half g_xf[Bc * Nn * DIMc];            // x as fp16
__device__ __half g_wqf[QKV_OUTc * DIMc];          // qkv_w as fp16
__device__ __half g_wpf[DIMc * VAL_ATTNc];         // proj_w as fp16
__device__ __half g_qf[Bc * Hh * Nn * KDc];        // [bh][n][32]
__device__ __half g_kf[Bc * Hh * Nn * KDc];
__device__ __half g_vf[Bc * Hh * Nn * VDc];        // [bh][n][128] row-major
__device__ __half g_of[Bc * Nn * VAL_ATTNc];       // attention output, fp16

// ---------------- helpers ----------------
static __device__ __forceinline__ unsigned pk_h2(float a, float b) {
    __half2 h = __floats2half2_rn(a, b);
    return *(unsigned*)&h;
}
static __device__ __forceinline__ void mma_f16(float* d, const unsigned* a, const unsigned* b) {
    asm("mma.sync.aligned.m16n8k16.row.col.f32.f16.f16.f32 "
        "{%0,%1,%2,%3}, {%4,%5,%6,%7}, {%8,%9}, {%0,%1,%2,%3};"
        : "+f"(d[0]), "+f"(d[1]), "+f"(d[2]), "+f"(d[3])
        : "r"(a[0]), "r"(a[1]), "r"(a[2]), "r"(a[3]), "r"(b[0]), "r"(b[1]));
}
static __device__ __forceinline__ uint32_t sm_u32(const void* p) {
    return (uint32_t)__cvta_generic_to_shared(p);
}
static __device__ __forceinline__ void ldsm4(unsigned* r, uint32_t a) {
    asm volatile("ldmatrix.sync.aligned.m8n8.x4.shared.b16 {%0,%1,%2,%3}, [%4];"
        : "=r"(r[0]), "=r"(r[1]), "=r"(r[2]), "=r"(r[3]) : "r"(a));
}
static __device__ __forceinline__ void ldsm4t(unsigned* r, uint32_t a) {
    asm volatile("ldmatrix.sync.aligned.m8n8.x4.trans.shared.b16 {%0,%1,%2,%3}, [%4];"
        : "=r"(r[0]), "=r"(r[1]), "=r"(r[2]), "=r"(r[3]) : "r"(a));
}
static __device__ __forceinline__ void cpa8(uint32_t d, const void* s, int sz) {
    asm volatile("cp.async.ca.shared.global [%0], [%1], 8, %2;"
        :: "r"(d), "l"(__cvta_generic_to_global(s)), "r"(sz) : "memory");
}
#define CP_COMMIT() asm volatile("cp.async.commit_group;" ::: "memory")
#define CP_WAIT0()  asm volatile("cp.async.wait_group 0;" ::: "memory")

// fast 2^t on fma/alu pipes (MUFU rt=8 is the softmax bottleneck otherwise)
static __device__ __forceinline__ float exp2_fast(float t) {
    t = fmaxf(t, -120.f);
    float r = t + 12582912.f;
    int n = __float_as_int(r) - 0x4B400000;
    float f = t - (r - 12582912.f);
    float g = f * 0.6931471805599453f;
    float p = fmaf(g, 0.0083333333f, 0.0416666667f);
    p = fmaf(p, g, 0.1666666667f);
    p = fmaf(p, g, 0.5f);
    p = fmaf(p, g, 1.0f);
    p = fmaf(p, g, 1.0f);
    return __int_as_float(__float_as_int(p) + (n << 23));
}

// ---------------- BN coefficient folding ----------------
__global__ void bn_coef_kernel(const float* __restrict__ qg, const float* __restrict__ qb,
                               const float* __restrict__ qm, const float* __restrict__ qv,
                               const float* __restrict__ pg, const float* __restrict__ pb,
                               const float* __restrict__ pm, const float* __restrict__ pv) {
    int i = blockIdx.x * 256 + threadIdx.x;
    if (i < QKV_OUTc) {
        float s = qg[i] * rsqrtf(qv[i] + 1e-5f);
        g_qs[i] = s;
        g_qbb[i] = qb[i] - qm[i] * s;
    }
    if (i < DIMc) {
        float s = pg[i] * rsqrtf(pv[i] + 1e-5f);
        g_ps[i] = s;
        g_pbb[i] = pb[i] - pm[i] * s;
    }
}

// ---------------- bias gather: bf16, pre-scaled by LOG2E ----------------
__global__ void bias_kernel(const float* __restrict__ ab, const int* __restrict__ idxs) {
    int nm = blockIdx.x * 256 + threadIdx.x;
    if (nm < Nn * Nn) {
        int idx = idxs[nm];
#pragma unroll
        for (int h = 0; h < Hh; h++)
            g_biasb[h * Nn * Nn + nm] = __float2bfloat16(ab[h * Nn + idx] * LOG2E);
    }
}

// ---------------- fp32 -> fp16 conversion (x, qkv_w, proj_w) ----------------
__global__ void cvt_f16_kernel(const float* __restrict__ s, int which, int n4) {
    int i = blockIdx.x * 256 + threadIdx.x;
    if (i >= n4) return;
    __half* d = (which == 0) ? g_xf : (which == 1) ? g_wqf : g_wpf;
    float4 v = ((const float4*)s)[i];
    ((uint2*)d)[i] = make_uint2(pk_h2(v.x, v.y), pk_h2(v.z, v.w));
}

// ---------------- qkv scatter: q,k,v -> fp16 ----------------
static __device__ __forceinline__ void qkv_scatter_f(int b, int n, int o, float y0, float y1) {
    int h = o / 192, r = o - h * 192;
    int bh = b * Hh + h;
    unsigned pk = pk_h2(y0, y1);
    __half* arr;
    size_t idx;
    if (r < KDc)            { arr = g_qf; idx = ((size_t)(bh * Nn) + n) * KDc + r; }
    else if (r < 2 * KDc)   { arr = g_kf; idx = ((size_t)(bh * Nn) + n) * KDc + (r - KDc); }
    else                    { arr = g_vf; idx = ((size_t)(bh * Nn) + n) * VDc + (r - 2 * KDc); }
    *(unsigned*)&arr[idx] = pk;
}

#define SSTR 40
#define G16STG 20480

// ---------------- fp16 single-product GEMM (qkv: mode 0, proj: mode 1) ----------------
__global__ __launch_bounds__(256, 2) void gemm_f16(int mode, float* __restrict__ out) {
    extern __shared__ __align__(16) char dsm[];
    int t = threadIdx.x;
    int lane = t & 31, wid = t >> 5;
    int g = lane >> 2, tg = lane & 3;
    int sub = lane >> 3, rr = lane & 7;
    int warp_m = wid >> 2, warp_n = wid & 3;
    int m0 = blockIdx.x * 128, o0 = blockIdx.y * 128;

    const __half *A, *B;
    int K;
    if (mode == 0) { A = g_xf; B = g_wqf; K = DIMc; }
    else           { A = g_of; B = g_wpf; K = VAL_ATTNc; }

    uint32_t sb = sm_u32(dsm);
    uint32_t a_off = (uint32_t)(((warp_m * 64 + (sub & 1) * 8 + rr) * SSTR + (sub >> 1) * 8) * 2);
    uint32_t b_off = 10240u +
        (uint32_t)(((warp_n * 32 + (sub >> 1) * 8 + rr) * SSTR + (sub & 1) * 8) * 2);

    float acc[4][4][4];
#pragma unroll
    for (int i = 0; i < 4; i++)
#pragma unroll
        for (int j = 0; j < 4; j++)
#pragma unroll
            for (int c = 0; c < 4; c++) acc[i][j][c] = 0.f;

    const int T = K >> 5;
#define Q_LOAD(IT, STG) do {                                                      \
        int _k0 = (IT) << 5;                                                      \
        uint32_t _base = sb + (STG) * G16STG;                                     \
        _Pragma("unroll")                                                         \
        for (int ii = 0; ii < 4; ii++) {                                          \
            int e = t + 256 * ii;                                                 \
            int r = e >> 3, c = e & 7;                                            \
            uint32_t so = _base + (uint32_t)(r * 80 + 8 * c);                     \
            cpa8(so,          A + (size_t)(m0 + r) * K + _k0 + 4 * c, 8);         \
            cpa8(so + 10240u, B + (size_t)(o0 + r) * K + _k0 + 4 * c, 8);         \
        }                                                                         \
        CP_COMMIT();                                                              \
    } while (0)

    Q_LOAD(0, 0);
    for (int it = 0; it < T; it++) {
        CP_WAIT0();
        __syncthreads();
        if (it + 1 < T) Q_LOAD(it + 1, (it + 1) & 1);
        uint32_t base = sb + (it & 1) * G16STG;
#pragma unroll
        for (int kk = 0; kk < 2; kk++) {
            unsigned ah[4][4], bb[2][4];
#pragma unroll
            for (int mi = 0; mi < 4; mi++)
                ldsm4(ah[mi], base + a_off + (uint32_t)((mi * 16 * SSTR + kk * 16) * 2));
#pragma unroll
            for (int njp = 0; njp < 2; njp++)
                ldsm4(bb[njp], base + b_off + (uint32_t)((njp * 16 * SSTR + kk * 16) * 2));
#pragma unroll
            for (int mi = 0; mi < 4; mi++)
#pragma unroll
                for (int njp = 0; njp < 2; njp++) {
                    mma_f16(acc[mi][2 * njp],     ah[mi], bb[njp]);
                    mma_f16(acc[mi][2 * njp + 1], ah[mi], bb[njp] + 2);
                }
        }
    }
#undef Q_LOAD

#pragma unroll
    for (int mi = 0; mi < 4; mi++) {
        int m_lo = m0 + warp_m * 64 + mi * 16 + g;
        int m_hi = m_lo + 8;
        if (mode == 0) {
            int b0 = m_lo / Nn, n0q = m_lo - b0 * Nn;
            int b1 = m_hi / Nn, n1q = m_hi - b1 * Nn;
#pragma unroll
            for (int nj = 0; nj < 4; nj++) {
                int o = o0 + warp_n * 32 + nj * 8 + 2 * tg;
                qkv_scatter_f(b0, n0q, o, acc[mi][nj][0] * g_qs[o] + g_qbb[o],
                                          acc[mi][nj][1] * g_qs[o + 1] + g_qbb[o + 1]);
                qkv_scatter_f(b1, n1q, o, acc[mi][nj][2] * g_qs[o] + g_qbb[o],
                                          acc[mi][nj][3] * g_qs[o + 1] + g_qbb[o + 1]);
            }
        } else {
#pragma unroll
            for (int nj = 0; nj < 4; nj++) {
                int o = o0 + warp_n * 32 + nj * 8 + 2 * tg;
                float s0 = g_ps[o], s1 = g_ps[o + 1];
                float c0 = g_pbb[o], c1 = g_pbb[o + 1];
                *(float2*)&out[(size_t)m_lo * DIMc + o] =
                    make_float2(acc[mi][nj][0] * s0 + c0, acc[mi][nj][1] * s1 + c1);
                *(float2*)&out[(size_t)m_hi * DIMc + o] =
                    make_float2(acc[mi][nj][2] * s0 + c0, acc[mi][nj][3] * s1 + c1);
            }
        }
    }
}

// ---------------- fp16 tensor-core attention ----------------
// dyn smem: Qf@0 (10240) | stage s @ 10240+s*22528: Kf@0 (5120), Vf@5120 (17408)
#define ASTG 22528
#define ATTN_SMEM_B 55296
#define VROWB 272

__global__ __launch_bounds__(256) void attn_mma_kernel() {
    extern __shared__ __align__(16) char dsm[];
    __half* Qf_s = (__half*)(dsm);

    int n0q = blockIdx.x * 128;
    int h = blockIdx.y, b = blockIdx.z;
    int bh = b * Hh + h;
    int t = threadIdx.x, w = t >> 5, lane = t & 31;
    int g = lane >> 2, tg = lane & 3;
    int sub = lane >> 3, rr = lane & 7;

    const __half* qfB = g_qf + (size_t)(bh * Nn) * KDc;
    const __half* kfB = g_kf + (size_t)(bh * Nn) * KDc;
    const __half* vfB = g_vf + (size_t)(bh * Nn) * VDc;
    const __nv_bfloat16* biasb = g_biasb + (size_t)h * Nn * Nn;

    uint32_t sb = sm_u32(dsm);
    uint32_t q_moff = (uint32_t)(((16 * w + (sub & 1) * 8 + rr) * SSTR + (sub >> 1) * 8) * 2);
    uint32_t k_lane = (uint32_t)((((sub >> 1) * 8 + rr) * SSTR + (sub & 1) * 8) * 2);
    uint32_t v_lane = (uint32_t)(((sub & 1) * 8 + rr) * VROWB + (sub >> 1) * 16);

    // load Q tile (128 x 32 fp16), rows clamped at boundary
#pragma unroll
    for (int e = t; e < 512; e += 256) {
        int r = e >> 2, c = e & 3;
        int n = n0q + r; if (n >= Nn) n = Nn - 1;
        *(uint4*)&Qf_s[r * SSTR + 8 * c] = *(const uint4*)&qfB[(size_t)n * KDc + 8 * c];
    }
    __syncthreads();

    // hoist Q fragments
    unsigned qf[2][4];
#pragma unroll
    for (int kt = 0; kt < 2; kt++)
        ldsm4(qf[kt], sb + q_moff + kt * 32);

#define KV_LOAD(IT, STG) do {                                                     \
        int _m0 = (IT) * 64;                                                      \
        uint32_t _base = sb + 10240u + (STG) * ASTG;                              \
        _Pragma("unroll")                                                         \
        for (int ii = 0; ii < 2; ii++) {                                          \
            int e = t + 256 * ii;                                                 \
            int r = e >> 3, c = e & 7;                                            \
            int m = _m0 + r;                                                      \
            int sz = (m < Nn) ? 8 : 0;                                            \
            int mc = (m < Nn) ? m : 0;                                            \
            cpa8(_base + (uint32_t)(r * 80 + 8 * c), kfB + (size_t)mc * KDc + 4 * c, sz); \
        }                                                                         \
        _Pragma("unroll")                                                         \
        for (int ii = 0; ii < 8; ii++) {                                          \
            int e = t + 256 * ii;                                                 \
            int r = e >> 5, c = e & 31;                                           \
            int m = _m0 + r;                                                      \
            int sz = (m < Nn) ? 8 : 0;                                            \
            int mc = (m < Nn) ? m : 0;                                            \
            cpa8(_base + 5120u + (uint32_t)(r * VROWB + 8 * c),                   \
                 vfB + (size_t)mc * VDc + 4 * c, sz);                             \
        }                                                                         \
        CP_COMMIT();                                                              \
    } while (0)

    float o_acc[16][4];
#pragma unroll
    for (int on = 0; on < 16; on++)
#pragma unroll
        for (int c = 0; c < 4; c++) o_acc[on][c] = 0.f;
    float rs0 = 0.f, rs1 = 0.f;

    int row0 = n0q + 16 * w + g;
    int nc0 = (row0 < Nn) ? row0 : (Nn - 1);
    int nc1 = (row0 + 8 < Nn) ? (row0 + 8) : (Nn - 1);

    const int T = (Nn + 63) / 64;   // 13
    KV_LOAD(0, 0);
    for (int it = 0; it < T; it++) {
        CP_WAIT0();
        __syncthreads();
        if (it + 1 < T) KV_LOAD(it + 1, (it + 1) & 1);
        int m0 = it * 64;
        uint32_t stb = sb + 10240u + (it & 1) * ASTG;
        uint32_t k_base = stb + k_lane;
        uint32_t v_base = stb + 5120u + v_lane;

        // ---- prefetch bias (bf16 pairs, pre-scaled by LOG2E) ----
        unsigned ub0[8], ub1[8];
#pragma unroll
        for (int nt = 0; nt < 8; nt++) {
            int mcol = m0 + 8 * nt + 2 * tg;
            if (mcol < Nn) {
                ub0[nt] = *(const unsigned*)&biasb[(size_t)nc0 * Nn + mcol];
                ub1[nt] = *(const unsigned*)&biasb[(size_t)nc1 * Nn + mcol];
            } else {
                ub0[nt] = 0xC6EAC6EAu;
                ub1[nt] = 0xC6EAC6EAu;
            }
        }

        // ---- S = Q K^T (fp16 single product) ----
        float sa[8][4];
#pragma unroll
        for (int nt = 0; nt < 8; nt++)
#pragma unroll
            for (int c = 0; c < 4; c++) sa[nt][c] = 0.f;
#pragma unroll
        for (int kt = 0; kt < 2; kt++) {
#pragma unroll
            for (int ntp = 0; ntp < 4; ntp++) {
                unsigned bb[4];
                ldsm4(bb, k_base + (uint32_t)(ntp * 16 * SSTR * 2 + kt * 32));
                mma_f16(sa[2 * ntp],     qf[kt], bb);
                mma_f16(sa[2 * ntp + 1], qf[kt], bb + 2);
            }
        }

        // ---- bias + exp (poly) -> fp16 P frags in registers ----
        unsigned pf[4][4];
#pragma unroll
        for (int nt = 0; nt < 8; nt++) {
            float b0lo = __uint_as_float(ub0[nt] << 16);
            float b0hi = __uint_as_float(ub0[nt] & 0xffff0000u);
            float b1lo = __uint_as_float(ub1[nt] << 16);
            float b1hi = __uint_as_float(ub1[nt] & 0xffff0000u);
            float p0 = exp2_fast(fmaf(sa[nt][0], SCALE * LOG2E, b0lo));
            float p1 = exp2_fast(fmaf(sa[nt][1], SCALE * LOG2E, b0hi));
            float p2 = exp2_fast(fmaf(sa[nt][2], SCALE * LOG2E, b1lo));
            float p3 = exp2_fast(fmaf(sa[nt][3], SCALE * LOG2E, b1hi));
            rs0 += p0 + p1;
            rs1 += p2 + p3;
            unsigned u01 = pk_h2(p0, p1), u23 = pk_h2(p2, p3);
            int kv = nt >> 1;
            if ((nt & 1) == 0) { pf[kv][0] = u01; pf[kv][1] = u23; }
            else               { pf[kv][2] = u01; pf[kv][3] = u23; }
        }

        // ---- O += P V (fp16; ldmatrix.trans on row-major V) ----
#pragma unroll
        for (int kv = 0; kv < 4; kv++) {
            uint32_t kvb = v_base + (uint32_t)(kv * 16 * VROWB);
#pragma unroll
            for (int op = 0; op < 8; op++) {
                unsigned vv[4];
                ldsm4t(vv, kvb + (uint32_t)(op * 32));
                mma_f16(o_acc[2 * op],     pf[kv], vv);
                mma_f16(o_acc[2 * op + 1], pf[kv], vv + 2);
            }
        }
    }
#undef KV_LOAD

    // reduce row sums across the 4 tg lanes of each group
    rs0 += __shfl_xor_sync(0xffffffffu, rs0, 1);
    rs0 += __shfl_xor_sync(0xffffffffu, rs0, 2);
    rs1 += __shfl_xor_sync(0xffffffffu, rs1, 1);
    rs1 += __shfl_xor_sync(0xffffffffu, rs1, 2);
    float inv0 = 1.f / rs0, inv1 = 1.f / rs1;

    // normalize + hardswish + store fp16 for proj GEMM
    int nlo = n0q + 16 * w + g, nhi = nlo + 8;
#pragma unroll
    for (int on = 0; on < 16; on++) {
        int d = h * VDc + 8 * on + 2 * tg;
        if (nlo < Nn) {
            float a0 = o_acc[on][0] * inv0, a1 = o_acc[on][1] * inv0;
            a0 = a0 * fminf(fmaxf(a0 + 3.f, 0.f), 6.f) * (1.f / 6.f);
            a1 = a1 * fminf(fmaxf(a1 + 3.f, 0.f), 6.f) * (1.f / 6.f);
            *(unsigned*)&g_of[((size_t)b * Nn + nlo) * VAL_ATTNc + d] = pk_h2(a0, a1);
        }
        if (nhi < Nn) {
            float a2 = o_acc[on][2] * inv1, a3 = o_acc[on][3] * inv1;
            a2 = a2 * fminf(fmaxf(a2 + 3.f, 0.f), 6.f) * (1.f / 6.f);
            a3 = a3 * fminf(fmaxf(a3 + 3.f, 0.f), 6.f) * (1.f / 6.f);
            *(unsigned*)&g_of[((size_t)b * Nn + nhi) * VAL_ATTNc + d] = pk_h2(a2, a3);
        }
    }
}

// ---------------- launch ----------------
extern "C" void kernel_launch(void* const* d_in, const int* in_sizes, int n_in,
                              void* d_out, int out_size) {
    (void)in_sizes; (void)n_in; (void)out_size;
    const float* x      = (const float*)d_in[0];
    const float* qkv_w  = (const float*)d_in[1];
    const float* qkv_g  = (const float*)d_in[2];
    const float* qkv_b  = (const float*)d_in[3];
    const float* qkv_m  = (const float*)d_in[4];
    const float* qkv_v  = (const float*)d_in[5];
    const float* ab     = (const float*)d_in[6];
    const float* proj_w = (const float*)d_in[7];
    const float* proj_g = (const float*)d_in[8];
    const float* proj_b = (const float*)d_in[9];
    const float* proj_m = (const float*)d_in[10];
    const float* proj_v = (const float*)d_in[11];
    const int*   idxs   = (const int*)d_in[12];
    float* out = (float*)d_out;

    bn_coef_kernel<<<6, 256>>>(qkv_g, qkv_b, qkv_m, qkv_v, proj_g, proj_b, proj_m, proj_v);
    bias_kernel<<<(Nn * Nn + 255) / 256, 256>>>(ab, idxs);

    cvt_f16_kernel<<<(Bc * Nn * DIMc / 4 + 255) / 256, 256>>>(x, 0, Bc * Nn * DIMc / 4);
    cvt_f16_kernel<<<(QKV_OUTc * DIMc / 4 + 255) / 256, 256>>>(qkv_w, 1, QKV_OUTc * DIMc / 4);
    cvt_f16_kernel<<<(DIMc * VAL_ATTNc / 4 + 255) / 256, 256>>>(proj_w, 2, DIMc * VAL_ATTNc / 4);

    gemm_f16<<<dim3(196, 12), 256, 2 * G16STG>>>(0, nullptr);   // QKV

    cudaFuncSetAttribute(attn_mma_kernel, cudaFuncAttributeMaxDynamicSharedMemorySize, ATTN_SMEM_B);
    attn_mma_kernel<<<dim3(7, Hh, Bc), 256, ATTN_SMEM_B>>>();

    gemm_f16<<<dim3(196, 4), 256, 2 * G16STG>>>(1, out);        // proj
}